// round 11
// baseline (speedup 1.0000x reference)
#include <cuda_runtime.h>
#include <math.h>

namespace {

typedef unsigned long long ull;

constexpr int T = 384;
constexpr int HALF = 192;

__device__ __forceinline__ ull fma2(ull a, ull b, ull c) {
    ull d; asm("fma.rn.f32x2 %0, %1, %2, %3;" : "=l"(d) : "l"(a), "l"(b), "l"(c));
    return d;
}
__device__ __forceinline__ ull add2(ull a, ull b) {
    ull d; asm("add.rn.f32x2 %0, %1, %2;" : "=l"(d) : "l"(a), "l"(b));
    return d;
}
__device__ __forceinline__ ull pk(float lo, float hi) {
    ull r; asm("mov.b64 %0, {%1, %2};" : "=l"(r) : "f"(lo), "f"(hi));
    return r;
}
__device__ __forceinline__ float2 upk(ull u) {
    float2 f; asm("mov.b64 {%0, %1}, %2;" : "=f"(f.x), "=f"(f.y) : "l"(u));
    return f;
}

// CTA = 2 warps = 64 lanes handling ONE packed neuron pair (A=.lo, B=.hi).
// Global lane gl (=tid) owns steps 6gl..6gl+5: NEGATED memory accumulators m[0..5].
// Warp0 = steps 0..191 (phase 1 serial recursion, 6 fma2/step scatter, publishes
// deltas per 12-step block). Warp1 = steps 192..383: during phase 1 it consumes
// W0's delta blocks and scatters them into its own half (dense, no zero-waste);
// in phase 2 it runs the recursion for the second half. Sync: smem flag + membar.
__global__ void __launch_bounds__(64) flif_kernel(
    const float* __restrict__ I,     // [S, T]
    const float* __restrict__ W,     // [4999]
    float* __restrict__ out_spk,     // [S, T]
    float* __restrict__ out_trc)     // [S, T]
{
    // wr[idx], idx in [-383,383]: wr[idx<=0]=0, wr[idx>0]=W[4999-idx].
    // Stored duplicated (w,w) at scrambled slot u+(u>>2), u = idx+384.
    __shared__ float2 wrx[960];
    __shared__ __align__(16) ull sIn[T];     // COEF*(I-1.75) packed (A,B)
    __shared__ __align__(16) ull strc[T];    // packed V trace
    __shared__ __align__(16) ull sdel[HALF]; // W0's NEGATED deltas (phase 1)
    __shared__ ull sV;                        // V at step 191 handoff
    __shared__ int sflag;                     // blocks published by W0 (0..16)

    const int tid  = threadIdx.x;
    const int lane = tid & 31;
    const int wid  = tid >> 5;
    const int g    = blockIdx.x;
    const int sA   = 2 * g, sB = 2 * g + 1;

    for (int u = tid; u < 768; u += 64) {
        int idx = u - 384;
        float v = (idx >= 1) ? W[4999 - idx] : 0.0f;
        wrx[u + (u >> 2)] = make_float2(v, v);
    }

    const float COEF = (float)(pow(0.1, 0.15) * tgamma(2.0 - 0.15) / 0.5);

    const float* IA = I + (size_t)sA * T;
    const float* IB = I + (size_t)sB * T;
    {
        const float4* ia = reinterpret_cast<const float4*>(IA);
        const float4* ib = reinterpret_cast<const float4*>(IB);
        for (int t = tid; t < 96; t += 64) {
            float4 a = ia[t], b = ib[t];
            sIn[4*t + 0] = pk(COEF * (a.x - 1.75f), COEF * (b.x - 1.75f));
            sIn[4*t + 1] = pk(COEF * (a.y - 1.75f), COEF * (b.y - 1.75f));
            sIn[4*t + 2] = pk(COEF * (a.z - 1.75f), COEF * (b.z - 1.75f));
            sIn[4*t + 3] = pk(COEF * (a.w - 1.75f), COEF * (b.w - 1.75f));
        }
    }
    const float rawA1 = IA[1];
    const float rawB1 = IB[1];
    if (tid == 0) sflag = 0;
    __syncthreads();

    const float af = (float)(1.0 - (double)COEF * 0.025);   // 1 - COEF*GL
    const ull A2   = pk(af, af);
    const ull NEG1 = pk(-1.0f, -1.0f);
    const ull* wrxu = reinterpret_cast<const ull*>(wrx);
    volatile int* vflag = (volatile int*)&sflag;

    if (wid == 0) {
        // ================= WARP 0: serial recursion, steps 0..191 =================
        ull m[6]; ull V, vhold, ndhold;
        #pragma unroll
        for (int j = 0; j < 6; ++j) m[j] = 0ull;

        // ---- block 0 (steps 0..11, with specials) ----
        {
            const int ub = 6 * lane + 384;
            ull wv[17];
            #pragma unroll
            for (int o = -11; o <= 5; ++o) { int idx = ub + o; wv[o + 11] = wrxu[idx + (idx >> 2)]; }
            ull In[12];
            {
                const ulonglong2* ip = reinterpret_cast<const ulonglong2*>(&sIn[0]);
                #pragma unroll
                for (int q = 0; q < 6; ++q) { ulonglong2 p = ip[q]; In[2*q] = p.x; In[2*q+1] = p.y; }
            }
            // step 0: V_pre=-70, V0=0 spikes -> Vn=-90; delta excluded (0)
            V = pk(-90.0f, -90.0f);
            vhold = V; ndhold = 0ull;
            // step 1: N==1 branch (V=-90, no spike -> no reset)
            {
                float2 v = upk(V);
                ull Vn = pk(v.x + 0.005f * (rawA1 / 0.025f - v.x),
                            v.y + 0.005f * (rawB1 / 0.025f - v.y));
                ull nd = fma2(Vn, NEG1, V);
                if (lane == 0) {
                    ulonglong2 pr; pr.x = vhold;  pr.y = Vn;
                    *reinterpret_cast<ulonglong2*>(&strc[0]) = pr;
                    ulonglong2 pd; pd.x = ndhold; pd.y = nd;
                    *reinterpret_cast<ulonglong2*>(&sdel[0]) = pd;
                }
                V = Vn;
                #pragma unroll
                for (int j = 0; j < 6; ++j)
                    m[j] = fma2(nd, wv[j - 1 + 11], m[j]);
            }
            // steps 2..11
            #pragma unroll
            for (int r = 2; r < 12; ++r) {
                ull mem = __shfl_sync(0xffffffffu, m[r % 6], (r >= 6) ? 1 : 0);
                float2 v = upk(V);
                ull nrst = pk(v.x > -50.0f ? -20.0f : 0.0f,
                              v.y > -50.0f ? -20.0f : 0.0f);
                ull Vq = fma2(A2, V, In[r]);
                ull Vp = add2(Vq, mem);
                ull Vn = add2(Vp, nrst);
                ull nd = fma2(Vn, NEG1, V);
                V = Vn;
                if (r & 1) {
                    if (lane == 0) {
                        ulonglong2 pr; pr.x = vhold;  pr.y = Vn;
                        *reinterpret_cast<ulonglong2*>(&strc[r - 1]) = pr;
                        ulonglong2 pd; pd.x = ndhold; pd.y = nd;
                        *reinterpret_cast<ulonglong2*>(&sdel[r - 1]) = pd;
                    }
                } else { vhold = Vn; ndhold = nd; }
                #pragma unroll
                for (int j = 0; j < 6; ++j)
                    m[j] = fma2(nd, wv[j - r + 11], m[j]);
            }
        }
        __threadfence_block();
        if (lane == 0) *vflag = 1;

        // ---- blocks 1..15 ----
        #pragma unroll 1
        for (int b = 1; b < 16; ++b) {
            const int ub = 6 * (lane - 2 * b) + 384;
            ull wv[17];
            #pragma unroll
            for (int o = -11; o <= 5; ++o) { int idx = ub + o; wv[o + 11] = wrxu[idx + (idx >> 2)]; }
            ull In[12];
            {
                const ulonglong2* ip = reinterpret_cast<const ulonglong2*>(&sIn[12 * b]);
                #pragma unroll
                for (int q = 0; q < 6; ++q) { ulonglong2 p = ip[q]; In[2*q] = p.x; In[2*q+1] = p.y; }
            }
            const int o0 = 2 * b, o1 = 2 * b + 1;
            #pragma unroll
            for (int r = 0; r < 12; ++r) {
                ull mem = __shfl_sync(0xffffffffu, m[r % 6], (r >= 6) ? o1 : o0);
                float2 v = upk(V);
                ull nrst = pk(v.x > -50.0f ? -20.0f : 0.0f,
                              v.y > -50.0f ? -20.0f : 0.0f);
                ull Vq = fma2(A2, V, In[r]);
                ull Vp = add2(Vq, mem);
                ull Vn = add2(Vp, nrst);
                ull nd = fma2(Vn, NEG1, V);
                V = Vn;
                if (r & 1) {
                    if (lane == 0) {
                        ulonglong2 pr; pr.x = vhold;  pr.y = Vn;
                        *reinterpret_cast<ulonglong2*>(&strc[12 * b + r - 1]) = pr;
                        ulonglong2 pd; pd.x = ndhold; pd.y = nd;
                        *reinterpret_cast<ulonglong2*>(&sdel[12 * b + r - 1]) = pd;
                    }
                } else { vhold = Vn; ndhold = nd; }
                #pragma unroll
                for (int j = 0; j < 6; ++j)
                    m[j] = fma2(nd, wv[j - r + 11], m[j]);
            }
            if (b < 15) {
                __threadfence_block();
                if (lane == 0) *vflag = b + 1;
            }
        }
        // handoff: V then final flag
        if (lane == 0) strc[HALF - 1 + 1 - 1] = strc[HALF - 1];  // no-op keep
        if (lane == 0) sV = V;
        __threadfence_block();
        if (lane == 0) *vflag = 16;
    } else {
        // ================= WARP 1 =================
        ull m[6];
        #pragma unroll
        for (int j = 0; j < 6; ++j) m[j] = 0ull;

        // ---- phase 1: consume W0's delta blocks, dense scatter into own half ----
        #pragma unroll 1
        for (int b = 0; b < 16; ++b) {
            while (*vflag < b + 1) __nanosleep(20);
            __threadfence_block();
            ull dd[12];
            {
                const ulonglong2* dp = reinterpret_cast<const ulonglong2*>(&sdel[12 * b]);
                #pragma unroll
                for (int q = 0; q < 6; ++q) { ulonglong2 p = dp[q]; dd[2*q] = p.x; dd[2*q+1] = p.y; }
            }
            const int ub = 6 * (32 + lane - 2 * b) + 384;   // ages all >= 1 (dense)
            ull wv[17];
            #pragma unroll
            for (int o = -11; o <= 5; ++o) { int idx = ub + o; wv[o + 11] = wrxu[idx + (idx >> 2)]; }
            #pragma unroll
            for (int r = 0; r < 12; ++r) {
                #pragma unroll
                for (int j = 0; j < 6; ++j)
                    m[j] = fma2(dd[r], wv[j - r + 11], m[j]);
            }
        }
        // wait for V handoff (flag 16 also covers sV + block-15 data)
        __threadfence_block();
        ull V = sV, vhold = 0ull;

        // ---- phase 2: serial recursion, steps 192..383 ----
        #pragma unroll 1
        for (int b = 0; b < 16; ++b) {
            const int ub = 6 * (lane - 2 * b) + 384;
            ull wv[17];
            #pragma unroll
            for (int o = -11; o <= 5; ++o) { int idx = ub + o; wv[o + 11] = wrxu[idx + (idx >> 2)]; }
            ull In[12];
            {
                const ulonglong2* ip = reinterpret_cast<const ulonglong2*>(&sIn[HALF + 12 * b]);
                #pragma unroll
                for (int q = 0; q < 6; ++q) { ulonglong2 p = ip[q]; In[2*q] = p.x; In[2*q+1] = p.y; }
            }
            const int o0 = 2 * b, o1 = 2 * b + 1;
            #pragma unroll
            for (int r = 0; r < 12; ++r) {
                ull mem = __shfl_sync(0xffffffffu, m[r % 6], (r >= 6) ? o1 : o0);
                float2 v = upk(V);
                ull nrst = pk(v.x > -50.0f ? -20.0f : 0.0f,
                              v.y > -50.0f ? -20.0f : 0.0f);
                ull Vq = fma2(A2, V, In[r]);
                ull Vp = add2(Vq, mem);
                ull Vn = add2(Vp, nrst);
                ull nd = fma2(Vn, NEG1, V);
                V = Vn;
                if (r & 1) {
                    if (lane == 0) {
                        ulonglong2 pr; pr.x = vhold; pr.y = Vn;
                        *reinterpret_cast<ulonglong2*>(&strc[HALF + 12 * b + r - 1]) = pr;
                    }
                } else vhold = Vn;
                #pragma unroll
                for (int j = 0; j < 6; ++j)
                    m[j] = fma2(nd, wv[j - r + 11], m[j]);
            }
        }
    }

    __syncthreads();

    // ---- epilogue: 64 lanes, each writes its 6 steps; spikes from trace ----
    ull pv = (tid == 0) ? 0ull : strc[6 * tid - 1];
    float2 p = upk(pv);
    float tA[6], tB[6], kA[6], kB[6];
    #pragma unroll
    for (int r = 0; r < 6; ++r) {
        float2 c = upk(strc[6 * tid + r]);
        tA[r] = c.x; tB[r] = c.y;
        kA[r] = (p.x > -50.0f) ? 1.0f : 0.0f;
        kB[r] = (p.y > -50.0f) ? 1.0f : 0.0f;
        p = c;
    }
    const int bo = 6 * tid;
    float2* psA = reinterpret_cast<float2*>(out_spk + (size_t)sA * T + bo);
    float2* psB = reinterpret_cast<float2*>(out_spk + (size_t)sB * T + bo);
    float2* ptA = reinterpret_cast<float2*>(out_trc + (size_t)sA * T + bo);
    float2* ptB = reinterpret_cast<float2*>(out_trc + (size_t)sB * T + bo);
    #pragma unroll
    for (int q = 0; q < 3; ++q) {
        psA[q] = make_float2(kA[2*q], kA[2*q+1]);
        psB[q] = make_float2(kB[2*q], kB[2*q+1]);
        ptA[q] = make_float2(tA[2*q], tA[2*q+1]);
        ptB[q] = make_float2(tB[2*q], tB[2*q+1]);
    }
}

} // namespace

extern "C" void kernel_launch(void* const* d_in, const int* in_sizes, int n_in,
                              void* d_out, int out_size) {
    const float* I = (const float*)d_in[0];     // [2048, 384]
    const float* W = (const float*)d_in[1];     // [4999]
    float* out = (float*)d_out;                 // [spk | trc]
    const int S = in_sizes[0] / T;              // 2048
    float* out_spk = out;
    float* out_trc = out + (size_t)S * T;
    flif_kernel<<<S / 2, 64>>>(I, W, out_spk, out_trc);
}

// round 12
// speedup vs baseline: 1.5117x; 1.5117x over previous
#include <cuda_runtime.h>
#include <math.h>

namespace {

typedef unsigned long long ull;

constexpr int T = 384;
constexpr int SLOTS = 12;     // 32 lanes * 12 = 384 steps

__device__ __forceinline__ ull fma2(ull a, ull b, ull c) {
    ull d; asm("fma.rn.f32x2 %0, %1, %2, %3;" : "=l"(d) : "l"(a), "l"(b), "l"(c));
    return d;
}
__device__ __forceinline__ ull add2(ull a, ull b) {
    ull d; asm("add.rn.f32x2 %0, %1, %2;" : "=l"(d) : "l"(a), "l"(b));
    return d;
}
__device__ __forceinline__ ull pk(float lo, float hi) {
    ull r; asm("mov.b64 %0, {%1, %2};" : "=l"(r) : "f"(lo), "f"(hi));
    return r;
}
__device__ __forceinline__ float2 upk(ull u) {
    float2 f; asm("mov.b64 {%0, %1}, %2;" : "=f"(f.x), "=f"(f.y) : "l"(u));
    return f;
}

// One warp = 2 neurons (A=.lo, B=.hi). Lane l owns NEGATED memory accumulators
// m[0..11] for steps 12l..12l+11. LOOKAHEAD SHFL: at step r we shfl the NEXT
// step's slot BEFORE this step's scatter touches it (32cy latency hidden under
// the step's issue stream) and repair the missing age-1 term with one fma2:
// mem_next = pre + wr[1]*nd_r. Uniform across block boundaries (age 12l0+11 ->
// 12(l0+1) is also 1). V-chain per step: mem -> Vn -> nd = 12cy.
__global__ void __launch_bounds__(32) flif_kernel(
    const float* __restrict__ I,     // [S, T]
    const float* __restrict__ W,     // [4999]
    float* __restrict__ out_spk,     // [S, T]
    float* __restrict__ out_trc)     // [S, T]
{
    // wr[idx], idx in [-383,383]: wr[idx<=0]=0, wr[idx>0]=W[4999-idx].
    // Stored duplicated (w,w) at scrambled slot u+(u>>2), u = idx+384.
    __shared__ float2 wrx[960];
    __shared__ __align__(16) ull sIn[T];   // COEF*(I-1.75) packed (A,B)
    __shared__ __align__(16) ull strc[T];  // packed V trace

    const int lane = threadIdx.x;
    const int g    = blockIdx.x;
    const int sA   = 2 * g, sB = 2 * g + 1;

    for (int u = lane; u < 768; u += 32) {
        int idx = u - 384;
        float v = (idx >= 1) ? W[4999 - idx] : 0.0f;
        wrx[u + (u >> 2)] = make_float2(v, v);
    }

    const float COEF = (float)(pow(0.1, 0.15) * tgamma(2.0 - 0.15) / 0.5);

    const float* IA = I + (size_t)sA * T;
    const float* IB = I + (size_t)sB * T;
    {
        const float4* ia = reinterpret_cast<const float4*>(IA);
        const float4* ib = reinterpret_cast<const float4*>(IB);
        #pragma unroll
        for (int q = 0; q < 3; ++q) {
            float4 a = ia[lane + 32 * q], b = ib[lane + 32 * q];
            int t = (lane + 32 * q) * 4;
            sIn[t + 0] = pk(COEF * (a.x - 1.75f), COEF * (b.x - 1.75f));
            sIn[t + 1] = pk(COEF * (a.y - 1.75f), COEF * (b.y - 1.75f));
            sIn[t + 2] = pk(COEF * (a.z - 1.75f), COEF * (b.z - 1.75f));
            sIn[t + 3] = pk(COEF * (a.w - 1.75f), COEF * (b.w - 1.75f));
        }
    }
    const float rawA1 = IA[1];   // raw inputs for the exact N==1 branch
    const float rawB1 = IB[1];
    __syncwarp();

    const float af = (float)(1.0 - (double)COEF * 0.025);   // 1 - COEF*GL
    const ull A2   = pk(af, af);
    const ull NEG1 = pk(-1.0f, -1.0f);

    const ull* wrxu = reinterpret_cast<const ull*>(wrx);
    const ull WNF1 = wrxu[(384 + 1) + ((384 + 1) >> 2)];   // wr[1] packed

    ull m[SLOTS];
    #pragma unroll
    for (int r = 0; r < SLOTS; ++r) m[r] = 0ull;

    ull V, mem, nrst, vhold;

    // ================= PEELED BLOCK l0 = 0 =================
    {
        const int ub = SLOTS * lane + 384;
        const int sb = ub + (ub >> 2);
        const bool mine = (lane == 0);

        ull wv[23];
        #pragma unroll
        for (int v = -11; v <= 11; ++v)
            wv[v + 11] = wrxu[sb + (v + (v >> 2))];

        ull In[SLOTS];
        {
            const ulonglong2* ip = reinterpret_cast<const ulonglong2*>(&sIn[0]);
            #pragma unroll
            for (int q = 0; q < 6; ++q) { ulonglong2 p = ip[q]; In[2*q] = p.x; In[2*q+1] = p.y; }
        }

        // step 0: V_pre=-70, V0=0 spikes -> Vn=-90; delta excluded
        V = pk(-90.0f, -90.0f);
        vhold = V;
        // step 1: N==1 branch (V=-90 -> no spike/reset); pre for step 2 is 0
        {
            float2 v = upk(V);
            ull Vn = pk(v.x + 0.005f * (rawA1 / 0.025f - v.x),
                        v.y + 0.005f * (rawB1 / 0.025f - v.y));
            ull nd = fma2(Vn, NEG1, V);
            if (mine) {
                ulonglong2 pr; pr.x = vhold; pr.y = Vn;
                *reinterpret_cast<ulonglong2*>(&strc[0]) = pr;
            }
            float2 vn = upk(Vn);
            nrst = pk(vn.x > -50.0f ? -20.0f : 0.0f,
                      vn.y > -50.0f ? -20.0f : 0.0f);
            V = Vn;
            #pragma unroll
            for (int j = 0; j < SLOTS; ++j)
                m[j] = fma2(nd, wv[j - 1 + 11], m[j]);
            mem = fma2(nd, WNF1, 0ull);      // pre = 0 (m[2] was untouched)
        }
        // steps 2..11
        #pragma unroll
        for (int r = 2; r < SLOTS; ++r) {
            ull pre = __shfl_sync(0xffffffffu, m[(r + 1) % SLOTS], (r < 11) ? 0 : 1);
            ull q  = add2(In[r], nrst);
            ull Vn = add2(fma2(A2, V, q), mem);
            ull nd = fma2(Vn, NEG1, V);
            float2 vn = upk(Vn);
            nrst = pk(vn.x > -50.0f ? -20.0f : 0.0f,
                      vn.y > -50.0f ? -20.0f : 0.0f);
            V = Vn;
            if (r & 1) {
                if (mine) {
                    ulonglong2 pr; pr.x = vhold; pr.y = Vn;
                    *reinterpret_cast<ulonglong2*>(&strc[r - 1]) = pr;
                }
            } else vhold = Vn;
            #pragma unroll
            for (int j = 0; j < SLOTS; ++j)
                m[j] = fma2(nd, wv[j - r + 11], m[j]);
            mem = fma2(nd, WNF1, pre);
        }
    }

    // ================= MAIN LOOP l0 = 1..31 (branch-free body) =================
    #pragma unroll 2
    for (int l0 = 1; l0 < 32; ++l0) {
        const int ubase = SLOTS * (lane - l0) + 384;   // multiple of 4
        const int sbase = ubase + (ubase >> 2);
        const bool mine = (lane == l0);

        ull wv[23];
        #pragma unroll
        for (int v = -11; v <= 11; ++v)
            wv[v + 11] = wrxu[sbase + (v + (v >> 2))];

        ull In[SLOTS];
        {
            const ulonglong2* ip = reinterpret_cast<const ulonglong2*>(&sIn[SLOTS * l0]);
            #pragma unroll
            for (int q = 0; q < 6; ++q) { ulonglong2 p = ip[q]; In[2*q] = p.x; In[2*q+1] = p.y; }
        }

        #pragma unroll
        for (int r = 0; r < SLOTS; ++r) {
            // lookahead: next step's slot, read BEFORE this step's scatter
            ull pre = __shfl_sync(0xffffffffu, m[(r + 1) % SLOTS], (r < 11) ? l0 : l0 + 1);

            ull q  = add2(In[r], nrst);              // nrst from previous Vn (off-chain)
            ull Vn = add2(fma2(A2, V, q), mem);      // chain: mem -> Vn
            ull nd = fma2(Vn, NEG1, V);              // NEGATED delta = V - Vn

            float2 vn = upk(Vn);
            nrst = pk(vn.x > -50.0f ? -20.0f : 0.0f,
                      vn.y > -50.0f ? -20.0f : 0.0f);
            V = Vn;

            if (r & 1) {
                if (mine) {
                    ulonglong2 pr; pr.x = vhold; pr.y = Vn;
                    *reinterpret_cast<ulonglong2*>(&strc[SLOTS * l0 + r - 1]) = pr;
                }
            } else vhold = Vn;

            // scatter to ALL owned slots: weight wr[12D + (j - r)]
            #pragma unroll
            for (int j = 0; j < SLOTS; ++j)
                m[j] = fma2(nd, wv[j - r + 11], m[j]);

            // repair lookahead with the age-1 term (bitwise-identical order)
            mem = fma2(nd, WNF1, pre);
        }
    }

    __syncwarp();

    // ---- outputs: spikes from stored trace (spike_n = V_{n-1} > -50), exact ----
    ull pv = (lane == 0) ? 0ull : strc[SLOTS * lane - 1];
    float2 p = upk(pv);
    float tA[SLOTS], tB[SLOTS], kA[SLOTS], kB[SLOTS];
    #pragma unroll
    for (int r = 0; r < SLOTS; ++r) {
        float2 c = upk(strc[SLOTS * lane + r]);
        tA[r] = c.x; tB[r] = c.y;
        kA[r] = (p.x > -50.0f) ? 1.0f : 0.0f;
        kB[r] = (p.y > -50.0f) ? 1.0f : 0.0f;
        p = c;
    }

    const int bo = lane * SLOTS;
    #pragma unroll
    for (int q = 0; q < 3; ++q) {
        reinterpret_cast<float4*>(out_spk + (size_t)sA * T + bo)[q] =
            make_float4(kA[4*q], kA[4*q+1], kA[4*q+2], kA[4*q+3]);
        reinterpret_cast<float4*>(out_spk + (size_t)sB * T + bo)[q] =
            make_float4(kB[4*q], kB[4*q+1], kB[4*q+2], kB[4*q+3]);
        reinterpret_cast<float4*>(out_trc + (size_t)sA * T + bo)[q] =
            make_float4(tA[4*q], tA[4*q+1], tA[4*q+2], tA[4*q+3]);
        reinterpret_cast<float4*>(out_trc + (size_t)sB * T + bo)[q] =
            make_float4(tB[4*q], tB[4*q+1], tB[4*q+2], tB[4*q+3]);
    }
}

} // namespace

extern "C" void kernel_launch(void* const* d_in, const int* in_sizes, int n_in,
                              void* d_out, int out_size) {
    const float* I = (const float*)d_in[0];     // [2048, 384]
    const float* W = (const float*)d_in[1];     // [4999]
    float* out = (float*)d_out;                 // [spk | trc]
    const int S = in_sizes[0] / T;              // 2048
    float* out_spk = out;
    float* out_trc = out + (size_t)S * T;
    flif_kernel<<<S / 2, 32>>>(I, W, out_spk, out_trc);
}

// round 13
// speedup vs baseline: 1.6179x; 1.0703x over previous
#include <cuda_runtime.h>
#include <math.h>

namespace {

typedef unsigned long long ull;

constexpr int T = 384;

__device__ __forceinline__ ull fma2(ull a, ull b, ull c) {
    ull d; asm("fma.rn.f32x2 %0, %1, %2, %3;" : "=l"(d) : "l"(a), "l"(b), "l"(c));
    return d;
}
__device__ __forceinline__ ull add2(ull a, ull b) {
    ull d; asm("add.rn.f32x2 %0, %1, %2;" : "=l"(d) : "l"(a), "l"(b));
    return d;
}
__device__ __forceinline__ ull pk(float lo, float hi) {
    ull r; asm("mov.b64 %0, {%1, %2};" : "=l"(r) : "f"(lo), "f"(hi));
    return r;
}
__device__ __forceinline__ float2 upk(ull u) {
    float2 f; asm("mov.b64 {%0, %1}, %2;" : "=f"(f.x), "=f"(f.y) : "l"(u));
    return f;
}

// One warp = 2 packed neurons (A=.lo, B=.hi). Three phases:
//  P1: serial steps 0..191. Lane l owns NEGATED accumulators m[0..5] for steps
//      6l..6l+5; 6-wide scatter; lane 0 publishes every delta to smem.
//  P2: m reinit; lane l now owns steps 192+6l..192+6l+5; dense rectangle:
//      all 192 published deltas scattered into the second-half slots (72
//      independent fma2 per 12-delta block, no zero weights).
//  P3: serial steps 192..383, 6-wide near scatter into the same m.
// Per-slot accumulation order identical to the full-width version (ascending n).
__global__ void __launch_bounds__(32) flif_kernel(
    const float* __restrict__ I,     // [S, T]
    const float* __restrict__ W,     // [4999]
    float* __restrict__ out_spk,     // [S, T]
    float* __restrict__ out_trc)     // [S, T]
{
    // wr[idx], idx in [-384,383]: wr[idx<=0]=0, wr[idx>0]=W[4999-idx].
    // Stored duplicated (w,w) at u = idx+384, NO scramble.
    __shared__ ull wr2[768];
    __shared__ __align__(16) ull sIn[T];    // COEF*(I-1.75) packed (A,B)
    __shared__ __align__(16) ull strc[T];   // packed V trace
    __shared__ __align__(16) ull sdel[192]; // packed NEGATED deltas, steps 0..191

    const int lane = threadIdx.x;
    const int g    = blockIdx.x;
    const int sA   = 2 * g, sB = 2 * g + 1;

    for (int u = lane; u < 768; u += 32) {
        float v = (u >= 385) ? W[4999 - (u - 384)] : 0.0f;
        wr2[u] = pk(v, v);
    }

    const float COEF = (float)(pow(0.1, 0.15) * tgamma(2.0 - 0.15) / 0.5);

    const float* IA = I + (size_t)sA * T;
    const float* IB = I + (size_t)sB * T;
    {
        const float4* ia = reinterpret_cast<const float4*>(IA);
        const float4* ib = reinterpret_cast<const float4*>(IB);
        #pragma unroll
        for (int q = 0; q < 3; ++q) {
            float4 a = ia[lane + 32 * q], b = ib[lane + 32 * q];
            int t = (lane + 32 * q) * 4;
            sIn[t + 0] = pk(COEF * (a.x - 1.75f), COEF * (b.x - 1.75f));
            sIn[t + 1] = pk(COEF * (a.y - 1.75f), COEF * (b.y - 1.75f));
            sIn[t + 2] = pk(COEF * (a.z - 1.75f), COEF * (b.z - 1.75f));
            sIn[t + 3] = pk(COEF * (a.w - 1.75f), COEF * (b.w - 1.75f));
        }
    }
    const float rawA1 = IA[1];
    const float rawB1 = IB[1];
    __syncwarp();

    const float af = (float)(1.0 - (double)COEF * 0.025);   // 1 - COEF*GL
    const ull A2   = pk(af, af);
    const ull NEG1 = pk(-1.0f, -1.0f);

    ull m[6];
    #pragma unroll
    for (int j = 0; j < 6; ++j) m[j] = 0ull;

    ull V, nrst, vhold, ndhold;

    // ===================== PHASE 1: serial steps 0..191 =====================
    // ---- block 0 (specials) ----
    {
        const ull* wp = wr2 + (6 * lane + 384);
        ull wv[17];
        #pragma unroll
        for (int o = -11; o <= 5; ++o) wv[o + 11] = wp[o];
        ull In[12];
        {
            const ulonglong2* ip = reinterpret_cast<const ulonglong2*>(&sIn[0]);
            #pragma unroll
            for (int q = 0; q < 6; ++q) { ulonglong2 p = ip[q]; In[2*q] = p.x; In[2*q+1] = p.y; }
        }
        // step 0: V_pre=-70, V0=0 spikes -> Vn=-90; delta excluded (0)
        V = pk(-90.0f, -90.0f);
        vhold = V; ndhold = 0ull;
        // step 1: N==1 branch (V=-90 -> no spike/reset)
        {
            float2 v = upk(V);
            ull Vn = pk(v.x + 0.005f * (rawA1 / 0.025f - v.x),
                        v.y + 0.005f * (rawB1 / 0.025f - v.y));
            ull nd = fma2(Vn, NEG1, V);
            if (lane == 0) {
                ulonglong2 pr; pr.x = vhold;  pr.y = Vn;
                *reinterpret_cast<ulonglong2*>(&strc[0]) = pr;
                ulonglong2 pd; pd.x = ndhold; pd.y = nd;
                *reinterpret_cast<ulonglong2*>(&sdel[0]) = pd;
            }
            float2 vn = upk(Vn);
            nrst = pk(vn.x > -50.0f ? -20.0f : 0.0f,
                      vn.y > -50.0f ? -20.0f : 0.0f);
            V = Vn;
            #pragma unroll
            for (int j = 0; j < 6; ++j)
                m[j] = fma2(nd, wv[j - 1 + 11], m[j]);
        }
        // steps 2..11
        #pragma unroll
        for (int r = 2; r < 12; ++r) {
            ull mem = __shfl_sync(0xffffffffu, m[r % 6], (r < 6) ? 0 : 1);
            ull Vq = fma2(A2, V, In[r]);
            ull Vp = add2(Vq, mem);
            ull Vn = add2(Vp, nrst);
            ull nd = fma2(Vn, NEG1, V);
            float2 vn = upk(Vn);
            nrst = pk(vn.x > -50.0f ? -20.0f : 0.0f,
                      vn.y > -50.0f ? -20.0f : 0.0f);
            V = Vn;
            if (r & 1) {
                if (lane == 0) {
                    ulonglong2 pr; pr.x = vhold;  pr.y = Vn;
                    *reinterpret_cast<ulonglong2*>(&strc[r - 1]) = pr;
                    ulonglong2 pd; pd.x = ndhold; pd.y = nd;
                    *reinterpret_cast<ulonglong2*>(&sdel[r - 1]) = pd;
                }
            } else { vhold = Vn; ndhold = nd; }
            #pragma unroll
            for (int j = 0; j < 6; ++j)
                m[j] = fma2(nd, wv[j - r + 11], m[j]);
        }
    }
    // ---- blocks 1..15 ----
    #pragma unroll 1
    for (int b = 1; b < 16; ++b) {
        const ull* wp = wr2 + (6 * (lane - 2 * b) + 384);
        ull wv[17];
        #pragma unroll
        for (int o = -11; o <= 5; ++o) wv[o + 11] = wp[o];
        ull In[12];
        {
            const ulonglong2* ip = reinterpret_cast<const ulonglong2*>(&sIn[12 * b]);
            #pragma unroll
            for (int q = 0; q < 6; ++q) { ulonglong2 p = ip[q]; In[2*q] = p.x; In[2*q+1] = p.y; }
        }
        const int o0 = 2 * b, o1 = 2 * b + 1;
        #pragma unroll
        for (int r = 0; r < 12; ++r) {
            ull mem = __shfl_sync(0xffffffffu, m[r % 6], (r < 6) ? o0 : o1);
            ull Vq = fma2(A2, V, In[r]);
            ull Vp = add2(Vq, mem);
            ull Vn = add2(Vp, nrst);
            ull nd = fma2(Vn, NEG1, V);
            float2 vn = upk(Vn);
            nrst = pk(vn.x > -50.0f ? -20.0f : 0.0f,
                      vn.y > -50.0f ? -20.0f : 0.0f);
            V = Vn;
            if (r & 1) {
                if (lane == 0) {
                    ulonglong2 pr; pr.x = vhold;  pr.y = Vn;
                    *reinterpret_cast<ulonglong2*>(&strc[12 * b + r - 1]) = pr;
                    ulonglong2 pd; pd.x = ndhold; pd.y = nd;
                    *reinterpret_cast<ulonglong2*>(&sdel[12 * b + r - 1]) = pd;
                }
            } else { vhold = Vn; ndhold = nd; }
            #pragma unroll
            for (int j = 0; j < 6; ++j)
                m[j] = fma2(nd, wv[j - r + 11], m[j]);
        }
    }
    __syncwarp();

    // ===================== PHASE 2: dense rectangle =====================
    // lane l now owns steps 192+6l..192+6l+5; add deltas 0..191 in order.
    #pragma unroll
    for (int j = 0; j < 6; ++j) m[j] = 0ull;
    #pragma unroll 1
    for (int b = 0; b < 16; ++b) {
        const ull* wp = wr2 + (6 * lane + 576 - 12 * b);
        ull wv[17];
        #pragma unroll
        for (int o = -11; o <= 5; ++o) wv[o + 11] = wp[o];
        ull dd[12];
        {
            const ulonglong2* dp = reinterpret_cast<const ulonglong2*>(&sdel[12 * b]);
            #pragma unroll
            for (int q = 0; q < 6; ++q) { ulonglong2 p = dp[q]; dd[2*q] = p.x; dd[2*q+1] = p.y; }
        }
        #pragma unroll
        for (int r = 0; r < 12; ++r) {
            #pragma unroll
            for (int j = 0; j < 6; ++j)
                m[j] = fma2(dd[r], wv[j - r + 11], m[j]);
        }
    }

    // ===================== PHASE 3: serial steps 192..383 =====================
    #pragma unroll 1
    for (int b = 0; b < 16; ++b) {
        const ull* wp = wr2 + (6 * (lane - 2 * b) + 384);
        ull wv[17];
        #pragma unroll
        for (int o = -11; o <= 5; ++o) wv[o + 11] = wp[o];
        ull In[12];
        {
            const ulonglong2* ip = reinterpret_cast<const ulonglong2*>(&sIn[192 + 12 * b]);
            #pragma unroll
            for (int q = 0; q < 6; ++q) { ulonglong2 p = ip[q]; In[2*q] = p.x; In[2*q+1] = p.y; }
        }
        const int o0 = 2 * b, o1 = 2 * b + 1;
        #pragma unroll
        for (int r = 0; r < 12; ++r) {
            ull mem = __shfl_sync(0xffffffffu, m[r % 6], (r < 6) ? o0 : o1);
            ull Vq = fma2(A2, V, In[r]);
            ull Vp = add2(Vq, mem);
            ull Vn = add2(Vp, nrst);
            ull nd = fma2(Vn, NEG1, V);
            float2 vn = upk(Vn);
            nrst = pk(vn.x > -50.0f ? -20.0f : 0.0f,
                      vn.y > -50.0f ? -20.0f : 0.0f);
            V = Vn;
            if (r & 1) {
                if (lane == 0) {
                    ulonglong2 pr; pr.x = vhold; pr.y = Vn;
                    *reinterpret_cast<ulonglong2*>(&strc[192 + 12 * b + r - 1]) = pr;
                }
            } else vhold = Vn;
            #pragma unroll
            for (int j = 0; j < 6; ++j)
                m[j] = fma2(nd, wv[j - r + 11], m[j]);
        }
    }
    __syncwarp();

    // ---- outputs: spikes from stored trace (spike_n = V_{n-1} > -50), exact ----
    ull pv = (lane == 0) ? 0ull : strc[12 * lane - 1];
    float2 p = upk(pv);
    float tA[12], tB[12], kA[12], kB[12];
    #pragma unroll
    for (int r = 0; r < 12; ++r) {
        float2 c = upk(strc[12 * lane + r]);
        tA[r] = c.x; tB[r] = c.y;
        kA[r] = (p.x > -50.0f) ? 1.0f : 0.0f;
        kB[r] = (p.y > -50.0f) ? 1.0f : 0.0f;
        p = c;
    }
    const int bo = lane * 12;
    #pragma unroll
    for (int q = 0; q < 3; ++q) {
        reinterpret_cast<float4*>(out_spk + (size_t)sA * T + bo)[q] =
            make_float4(kA[4*q], kA[4*q+1], kA[4*q+2], kA[4*q+3]);
        reinterpret_cast<float4*>(out_spk + (size_t)sB * T + bo)[q] =
            make_float4(kB[4*q], kB[4*q+1], kB[4*q+2], kB[4*q+3]);
        reinterpret_cast<float4*>(out_trc + (size_t)sA * T + bo)[q] =
            make_float4(tA[4*q], tA[4*q+1], tA[4*q+2], tA[4*q+3]);
        reinterpret_cast<float4*>(out_trc + (size_t)sB * T + bo)[q] =
            make_float4(tB[4*q], tB[4*q+1], tB[4*q+2], tB[4*q+3]);
    }
}

} // namespace

extern "C" void kernel_launch(void* const* d_in, const int* in_sizes, int n_in,
                              void* d_out, int out_size) {
    const float* I = (const float*)d_in[0];     // [2048, 384]
    const float* W = (const float*)d_in[1];     // [4999]
    float* out = (float*)d_out;                 // [spk | trc]
    const int S = in_sizes[0] / T;              // 2048
    float* out_spk = out;
    float* out_trc = out + (size_t)S * T;
    flif_kernel<<<S / 2, 32>>>(I, W, out_spk, out_trc);
}